// round 8
// baseline (speedup 1.0000x reference)
#include <cuda_runtime.h>
#include <math.h>

#define S   192
#define H   64
#define NH  8
#define SS  (S*S)    // 36864
#define SH  (S*H)    // 12288
#define SCALE 0.125f
#define NEGF (-1000000.0f)

// Output offsets (flattened concat of reference tuple: z, score, v_gated, M)
#define OFF_Z     0
#define OFF_SCORE 98304          // 8*192*64
#define OFF_VG    56721408       // + 8*192*192*192
#define OFF_M     75595776       // + 8*192*192*64

// ---- device scratch (no allocs allowed) ----
__device__ float g_qk [NH*SS];   // [n][t][q]
__device__ float g_qkT[NH*SS];   // [n][q][t]
__device__ float g_kk [NH*SS];   // [n][s][t]
__device__ float g_sv1[NH*SH];   // silu(v1)
__device__ float g_B  [NH*SH];   // v2[t,h] * sum_{s<=t} exp(scale*kk[s,t])*sv1[s,h]
__device__ float g_E  [NH*S];    // sum_{s<=t} exp(scale*kk[s,t])
__device__ float g_Mkk[NH*S];    // max_{s<=t} scale*kk[s,t]

// ---------------------------------------------------------------------------
// K1: both Gram matrices. z<8: qk (head z, + transposed copy); z>=8: kk.
__global__ void k_gram(const float* __restrict__ qm, const float* __restrict__ k1,
                       const float* __restrict__ k2) {
    int z = blockIdx.z;
    int n = z & 7;
    bool is_kk = z >= 8;
    const float* A = (is_kk ? k1 : k2) + n*SH;
    const float* B = (is_kk ? k2 : qm) + n*SH;
    float* C = (is_kk ? g_kk : g_qk) + n*SS;
    __shared__ float As[16][17], Bs[16][17];
    int ty = threadIdx.y, tx = threadIdx.x;
    int row = blockIdx.y*16 + ty;
    float acc = 0.f;
    #pragma unroll
    for (int k0 = 0; k0 < H; k0 += 16) {
        As[ty][tx] = A[row*H + k0 + tx];
        Bs[ty][tx] = B[(blockIdx.x*16 + ty)*H + k0 + tx];
        __syncthreads();
        #pragma unroll
        for (int k = 0; k < 16; k++) acc += As[ty][k]*Bs[tx][k];
        __syncthreads();
    }
    C[row*S + blockIdx.x*16 + tx] = acc;
    if (!is_kk) {
        __syncthreads();
        As[ty][tx] = acc;
        __syncthreads();
        g_qkT[n*SS + (blockIdx.x*16 + ty)*S + blockIdx.y*16 + tx] = As[tx][ty];
    }
}

// ---------------------------------------------------------------------------
__global__ void k_silu(const float* __restrict__ v1) {
    int i = blockIdx.x*256 + threadIdx.x;
    float x = v1[i];
    g_sv1[i] = x / (1.f + __expf(-x));
}

// ---------------------------------------------------------------------------
// K2b (tiled masked GEMM): per block (ttile of 32, head n), 256 threads.
//   B[t,h] = v2[t,h] * sum_{s<=t} e(s,t)*sv1[s,h];  E[t]; Mkk[t].
__global__ void k_accumB(const float* __restrict__ v2) {
    int n = blockIdx.y;
    int t0 = blockIdx.x * 32;
    int tid = threadIdx.x;
    __shared__ float sv [32][64];    // sv1 s-tile
    __shared__ float esh[32][33];    // masked exp
    __shared__ float xsh[32][33];    // raw scaled scores (for Mkk)
    int t  = tid & 31;               // local t
    int hb = (tid >> 5) * 8;         // h base (8 contiguous h per thread)
    int gt = t0 + t;
    float acc[8];
    #pragma unroll
    for (int j = 0; j < 8; j++) acc[j] = 0.f;
    float Et = 0.f, Mk = -3.0e38f;

    int nTiles = t0/32 + 1;
    const float* sv1h = g_sv1 + n*SH;
    const float* kkh  = g_kk + n*SS;
    for (int st = 0; st < nTiles; st++) {
        int s0 = st * 32;
        // stage sv1[s0:s0+32][0:64]
        const float4* src = (const float4*)(sv1h + s0*H);
        float4* dst = (float4*)&sv[0][0];
        #pragma unroll
        for (int i = 0; i < 2; i++) dst[tid + i*256] = src[tid + i*256];
        // compute e, x for 32s x 32t
        int sLoc = tid >> 5;
        #pragma unroll
        for (int i = 0; i < 4; i++) {
            int s = sLoc + i*8;
            float xv = SCALE * kkh[(s0 + s)*S + gt];
            xsh[s][t] = xv;
            esh[s][t] = (s0 + s <= gt) ? __expf(xv) : 0.f;
        }
        __syncthreads();
        #pragma unroll 8
        for (int s = 0; s < 32; s++) {
            float e = esh[s][t];
            #pragma unroll
            for (int j = 0; j < 8; j++) acc[j] += e * sv[s][hb + j];
        }
        if (tid < 32) {
            #pragma unroll 8
            for (int s = 0; s < 32; s++) {
                Et += esh[s][t];
                if (s0 + s <= gt) Mk = fmaxf(Mk, xsh[s][t]);
            }
        }
        __syncthreads();
    }
    const float* v2h = v2 + n*SH + gt*H + hb;
    float* Bo = g_B + n*SH + gt*H + hb;
    #pragma unroll
    for (int j = 0; j < 8; j++) Bo[j] = acc[j] * v2h[j];
    if (tid < 32) { g_E[n*S + gt] = Et; g_Mkk[n*S + gt] = Mk; }
}

// ---------------------------------------------------------------------------
// K3 (fused stats + z), 8 q per block, B head tile staged in smem.
__global__ void k_qz(float* __restrict__ out) {
    extern __shared__ float sm[];
    float* Bsh  = sm;                // SH floats
    float* Mkks = Bsh + SH;          // S
    float* Es   = Mkks + S;          // S
    float* sw   = Es + S;            // S
    float* red  = sw + S;            // 9
    float* zp   = red + 9;           // 3*H

    int n = blockIdx.y, q0 = blockIdx.x * 8;
    int tid = threadIdx.x;
    int lane = tid & 31, warp = tid >> 5;

    // stage B, Mkk, E
    const float4* Bg = (const float4*)(g_B + n*SH);
    float4* B4 = (float4*)Bsh;
    #pragma unroll
    for (int i = 0; i < SH/4/256; i++) B4[tid + i*256] = Bg[tid + i*256];
    if (tid < S) { Mkks[tid] = g_Mkk[n*S + tid]; Es[tid] = g_E[n*S + tid]; }
    __syncthreads();

    int g = tid >> 6, h = tid & 63;
    const float* Bp = Bsh + (g*48)*H + h;
    const float* wp = sw + g*48;

    for (int qq = 0; qq < 8; qq++) {
        int q = q0 + qq;
        float x = 0.f;
        if (tid < S) x = SCALE * g_qkT[n*SS + q*S + tid];
        float cand = (tid < S && tid <= q) ? x + Mkks[tid] : -3.0e38f;
        float v = cand;
        #pragma unroll
        for (int o = 16; o; o >>= 1) v = fmaxf(v, __shfl_xor_sync(~0u, v, o));
        if (lane == 0) red[warp] = v;
        __syncthreads();
        if (tid == 0) {
            float r = red[0];
            #pragma unroll
            for (int i = 1; i < 8; i++) r = fmaxf(r, red[i]);
            red[8] = r;
        }
        __syncthreads();
        float m = red[8];
        float w = (tid < S && tid <= q) ? __expf(x - m) : 0.f;
        if (tid < S) sw[tid] = w;
        float lt = (tid < S) ? w * Es[tid] : 0.f;
        #pragma unroll
        for (int o = 16; o; o >>= 1) lt += __shfl_xor_sync(~0u, lt, o);
        if (lane == 0) red[warp] = lt;
        __syncthreads();                         // publishes sw too
        if (tid == 0) {
            float L = red[0];
            #pragma unroll
            for (int i = 1; i < 8; i++) L += red[i];
            red[8] = L;
            out[OFF_M + n*S + q] = m + logf(L + 0.01f);
        }
        __syncthreads();
        float L = red[8];
        float acc = 0.f;
        #pragma unroll 8
        for (int k = 0; k < 48; k++) acc += wp[k] * Bp[k*H];
        if (g) zp[(g-1)*H + h] = acc;
        __syncthreads();
        if (!g)
            out[OFF_Z + (n*S + q)*H + h] =
                (acc + zp[0*H + h] + zp[1*H + h] + zp[2*H + h]) / L;
        __syncthreads();
    }
}

// ---------------------------------------------------------------------------
// K4 (big): score[n][s][t][q] = (s<=t && t<=q) ? kk[s,t]+qk[t,q] : -1e6.
__global__ void k_score(float* __restrict__ out) {
    int n = blockIdx.y, t = blockIdx.x;
    int tid = threadIdx.x;                       // 192 threads
    __shared__ __align__(16) float qkt[S];
    __shared__ float kkc[S];
    qkt[tid] = g_qk[n*SS + t*S + tid];
    kkc[tid] = g_kk[n*SS + tid*S + t];
    __syncthreads();
    int qi4 = tid % 48;
    int so  = tid / 48;
    int q0  = qi4 * 4;
    float4 qv = *(const float4*)&qkt[q0];
    bool m0 = (t <= q0 + 0), m1 = (t <= q0 + 1),
         m2 = (t <= q0 + 2), m3 = (t <= q0 + 3);
    float* base = out + OFF_SCORE + n*(S*SS) + t*S;
    #pragma unroll 4
    for (int s = so; s < S; s += 4) {
        float kkv = kkc[s];
        bool sok = (s <= t);
        float4 v;
        v.x = (sok && m0) ? kkv + qv.x : NEGF;
        v.y = (sok && m1) ? kkv + qv.y : NEGF;
        v.z = (sok && m2) ? kkv + qv.z : NEGF;
        v.w = (sok && m3) ? kkv + qv.w : NEGF;
        *(float4*)&base[s*SS + q0] = v;
    }
}

// ---------------------------------------------------------------------------
// K5 (big): v_gated[n][s][t][h] = silu(v1)[s,h] * v2[t,h].
__global__ void k_vgated(const float* __restrict__ v2, float* __restrict__ out) {
    int n = blockIdx.y, s = blockIdx.x;
    int tid = threadIdx.x;                       // 256 threads
    int h4 = tid % 16, to = tid / 16;
    const float4* sv1r = (const float4*)(g_sv1 + n*SH + s*H);
    float4 s1 = sv1r[h4];
    const float4* v2h = (const float4*)(v2 + n*SH);
    float4* ob = (float4*)(out + OFF_VG + (n*S + s)*SH);
    #pragma unroll 4
    for (int t = to; t < S; t += 16) {
        float4 v = v2h[t*16 + h4];
        float4 r;
        r.x = s1.x * v.x; r.y = s1.y * v.y;
        r.z = s1.z * v.z; r.w = s1.w * v.w;
        ob[t*16 + h4] = r;
    }
}

// ---------------------------------------------------------------------------
static cudaStream_t s_aux = 0;
static cudaEvent_t  s_e0 = 0, s_e1 = 0;

extern "C" void kernel_launch(void* const* d_in, const int* in_sizes, int n_in,
                              void* d_out, int out_size) {
    const float* q  = (const float*)d_in[0];
    const float* k1 = (const float*)d_in[1];
    const float* k2 = (const float*)d_in[2];
    const float* v1 = (const float*)d_in[3];
    const float* v2 = (const float*)d_in[4];
    float* out = (float*)d_out;

    if (!s_aux) {   // host-side resources only; created on the (uncaptured) correctness run
        cudaStreamCreateWithFlags(&s_aux, cudaStreamNonBlocking);
        cudaEventCreateWithFlags(&s_e0, cudaEventDisableTiming);
        cudaEventCreateWithFlags(&s_e1, cudaEventDisableTiming);
        cudaFuncSetAttribute(k_qz, cudaFuncAttributeMaxDynamicSharedMemorySize, 56*1024);
    }
    const int QZ_SMEM = (SH + 3*S + 9 + 3*H) * sizeof(float);

    // shared prologue
    k_gram<<<dim3(12, 12, 16), dim3(16, 16)>>>(q, k1, k2);
    k_silu<<<(NH*SH)/256, 256>>>(v1);

    // fork: big streaming writers on aux stream
    cudaEventRecord(s_e0, 0);
    cudaStreamWaitEvent(s_aux, s_e0, 0);
    k_score <<<dim3(S, NH), 192, 0, s_aux>>>(out);
    k_vgated<<<dim3(S, NH), 256, 0, s_aux>>>(v2, out);
    cudaEventRecord(s_e1, s_aux);

    // stats chain on main stream (overlaps with the writers)
    k_accumB<<<dim3(6, NH), 256>>>(v2);
    k_qz    <<<dim3(24, NH), 256, QZ_SMEM>>>(out);

    // join
    cudaStreamWaitEvent(0, s_e1, 0);
}

// round 10
// speedup vs baseline: 1.0788x; 1.0788x over previous
#include <cuda_runtime.h>
#include <math.h>

#define S   192
#define H   64
#define NH  8
#define SS  (S*S)    // 36864
#define SH  (S*H)    // 12288
#define SCALE 0.125f
#define NEGF (-1000000.0f)

// Output offsets (flattened concat of reference tuple: z, score, v_gated, M)
#define OFF_Z     0
#define OFF_SCORE 98304          // 8*192*64
#define OFF_VG    56721408       // + 8*192*192*192
#define OFF_M     75595776       // + 8*192*192*64

// ---- device scratch (no allocs allowed) ----
__device__ float g_qk [NH*SS];   // [n][t][q]
__device__ float g_qkT[NH*SS];   // [n][q][t]
__device__ float g_kk [NH*SS];   // [n][s][t]
__device__ float g_sv1[NH*SH];   // silu(v1)
__device__ float g_B  [NH*SH];   // v2[t,h] * sum_{s<=t} exp(scale*kk[s,t])*sv1[s,h]
__device__ float g_E  [NH*S];    // sum_{s<=t} exp(scale*kk[s,t])
__device__ float g_Mkk[NH*S];    // max_{s<=t} scale*kk[s,t]

// ---------------------------------------------------------------------------
// K1: both Gram matrices. z<8: qk (head z, + transposed copy); z>=8: kk.
__global__ void k_gram(const float* __restrict__ qm, const float* __restrict__ k1,
                       const float* __restrict__ k2) {
    int z = blockIdx.z;
    int n = z & 7;
    bool is_kk = z >= 8;
    const float* A = (is_kk ? k1 : k2) + n*SH;
    const float* B = (is_kk ? k2 : qm) + n*SH;
    float* C = (is_kk ? g_kk : g_qk) + n*SS;
    __shared__ float As[16][17], Bs[16][17];
    int ty = threadIdx.y, tx = threadIdx.x;
    int row = blockIdx.y*16 + ty;
    float acc = 0.f;
    #pragma unroll
    for (int k0 = 0; k0 < H; k0 += 16) {
        As[ty][tx] = A[row*H + k0 + tx];
        Bs[ty][tx] = B[(blockIdx.x*16 + ty)*H + k0 + tx];
        __syncthreads();
        #pragma unroll
        for (int k = 0; k < 16; k++) acc += As[ty][k]*Bs[tx][k];
        __syncthreads();
    }
    C[row*S + blockIdx.x*16 + tx] = acc;
    if (!is_kk) {
        __syncthreads();
        As[ty][tx] = acc;
        __syncthreads();
        g_qkT[n*SS + (blockIdx.x*16 + ty)*S + blockIdx.y*16 + tx] = As[tx][ty];
    }
}

// ---------------------------------------------------------------------------
__global__ void k_silu(const float* __restrict__ v1) {
    int i = blockIdx.x*256 + threadIdx.x;
    float x = v1[i];
    g_sv1[i] = x / (1.f + __expf(-x));
}

// ---------------------------------------------------------------------------
// K4 (big): score[n][s][t][q] = (s<=t && t<=q) ? kk[s,t]+qk[t,q] : -1e6.
// Block per (n,t): stages qk[t,:] and kk[:,t] in smem -> streaming STG.128.CS.
__global__ void k_score(float* __restrict__ out) {
    int n = blockIdx.y, t = blockIdx.x;
    int tid = threadIdx.x;                       // 192 threads
    __shared__ __align__(16) float qkt[S];
    __shared__ float kkc[S];
    qkt[tid] = g_qk[n*SS + t*S + tid];
    kkc[tid] = g_kk[n*SS + tid*S + t];
    __syncthreads();
    int qi4 = tid % 48;
    int so  = tid / 48;
    int q0  = qi4 * 4;
    float4 qv = *(const float4*)&qkt[q0];
    bool m0 = (t <= q0 + 0), m1 = (t <= q0 + 1),
         m2 = (t <= q0 + 2), m3 = (t <= q0 + 3);
    float* base = out + OFF_SCORE + n*(S*SS) + t*S;
    #pragma unroll 8
    for (int s = so; s < S; s += 4) {
        float kkv = kkc[s];
        bool sok = (s <= t);
        float4 v;
        v.x = (sok && m0) ? kkv + qv.x : NEGF;
        v.y = (sok && m1) ? kkv + qv.y : NEGF;
        v.z = (sok && m2) ? kkv + qv.z : NEGF;
        v.w = (sok && m3) ? kkv + qv.w : NEGF;
        __stcs((float4*)&base[s*SS + q0], v);
    }
}

// ---------------------------------------------------------------------------
// K5 (big): v_gated[n][s][t][h] = silu(v1)[s,h] * v2[t,h]. Streaming stores.
__global__ void k_vgated(const float* __restrict__ v2, float* __restrict__ out) {
    int n = blockIdx.y, s = blockIdx.x;
    int tid = threadIdx.x;                       // 256 threads
    int h4 = tid % 16, to = tid / 16;
    const float4* sv1r = (const float4*)(g_sv1 + n*SH + s*H);
    float4 s1 = sv1r[h4];
    const float4* v2h = (const float4*)(v2 + n*SH);
    float4* ob = (float4*)(out + OFF_VG + (n*S + s)*SH);
    #pragma unroll 6
    for (int t = to; t < S; t += 16) {
        float4 v = __ldg(&v2h[t*16 + h4]);
        float4 r;
        r.x = s1.x * v.x; r.y = s1.y * v.y;
        r.z = s1.z * v.z; r.w = s1.w * v.w;
        __stcs(&ob[t*16 + h4], r);
    }
}

// ---------------------------------------------------------------------------
// K2b (tiled masked GEMM): per block (ttile of 32, head n), 256 threads.
//   B[t,h] = v2[t,h] * sum_{s<=t} e(s,t)*sv1[s,h];  E[t]; Mkk[t].
__global__ void k_accumB(const float* __restrict__ v2) {
    int n = blockIdx.y;
    int t0 = blockIdx.x * 32;
    int tid = threadIdx.x;
    __shared__ float sv [32][64];    // sv1 s-tile
    __shared__ float esh[32][33];    // masked exp
    __shared__ float xsh[32][33];    // raw scaled scores (for Mkk)
    int t  = tid & 31;               // local t
    int hb = (tid >> 5) * 8;         // h base (8 contiguous h per thread)
    int gt = t0 + t;
    float acc[8];
    #pragma unroll
    for (int j = 0; j < 8; j++) acc[j] = 0.f;
    float Et = 0.f, Mk = -3.0e38f;

    int nTiles = t0/32 + 1;
    const float* sv1h = g_sv1 + n*SH;
    const float* kkh  = g_kk + n*SS;
    for (int st = 0; st < nTiles; st++) {
        int s0 = st * 32;
        const float4* src = (const float4*)(sv1h + s0*H);
        float4* dst = (float4*)&sv[0][0];
        #pragma unroll
        for (int i = 0; i < 2; i++) dst[tid + i*256] = src[tid + i*256];
        int sLoc = tid >> 5;
        #pragma unroll
        for (int i = 0; i < 4; i++) {
            int s = sLoc + i*8;
            float xv = SCALE * kkh[(s0 + s)*S + gt];
            xsh[s][t] = xv;
            esh[s][t] = (s0 + s <= gt) ? __expf(xv) : 0.f;
        }
        __syncthreads();
        #pragma unroll 8
        for (int s = 0; s < 32; s++) {
            float e = esh[s][t];
            #pragma unroll
            for (int j = 0; j < 8; j++) acc[j] += e * sv[s][hb + j];
        }
        if (tid < 32) {
            #pragma unroll 8
            for (int s = 0; s < 32; s++) {
                Et += esh[s][t];
                if (s0 + s <= gt) Mk = fmaxf(Mk, xsh[s][t]);
            }
        }
        __syncthreads();
    }
    const float* v2h = v2 + n*SH + gt*H + hb;
    float* Bo = g_B + n*SH + gt*H + hb;
    #pragma unroll
    for (int j = 0; j < 8; j++) Bo[j] = acc[j] * v2h[j];
    if (tid < 32) { g_E[n*S + gt] = Et; g_Mkk[n*S + gt] = Mk; }
}

// ---------------------------------------------------------------------------
// K3 (fused stats + z), 8 q per block, B head tile staged in smem.
__global__ void k_qz(float* __restrict__ out) {
    extern __shared__ float sm[];
    float* Bsh  = sm;                // SH floats
    float* Mkks = Bsh + SH;          // S
    float* Es   = Mkks + S;          // S
    float* sw   = Es + S;            // S
    float* red  = sw + S;            // 9
    float* zp   = red + 9;           // 3*H

    int n = blockIdx.y, q0 = blockIdx.x * 8;
    int tid = threadIdx.x;
    int lane = tid & 31, warp = tid >> 5;

    const float4* Bg = (const float4*)(g_B + n*SH);
    float4* B4 = (float4*)Bsh;
    #pragma unroll
    for (int i = 0; i < SH/4/256; i++) B4[tid + i*256] = Bg[tid + i*256];
    if (tid < S) { Mkks[tid] = g_Mkk[n*S + tid]; Es[tid] = g_E[n*S + tid]; }
    __syncthreads();

    int g = tid >> 6, h = tid & 63;
    const float* Bp = Bsh + (g*48)*H + h;
    const float* wp = sw + g*48;

    for (int qq = 0; qq < 8; qq++) {
        int q = q0 + qq;
        float x = 0.f;
        if (tid < S) x = SCALE * g_qkT[n*SS + q*S + tid];
        float cand = (tid < S && tid <= q) ? x + Mkks[tid] : -3.0e38f;
        float v = cand;
        #pragma unroll
        for (int o = 16; o; o >>= 1) v = fmaxf(v, __shfl_xor_sync(~0u, v, o));
        if (lane == 0) red[warp] = v;
        __syncthreads();
        if (tid == 0) {
            float r = red[0];
            #pragma unroll
            for (int i = 1; i < 8; i++) r = fmaxf(r, red[i]);
            red[8] = r;
        }
        __syncthreads();
        float m = red[8];
        float w = (tid < S && tid <= q) ? __expf(x - m) : 0.f;
        if (tid < S) sw[tid] = w;
        float lt = (tid < S) ? w * Es[tid] : 0.f;
        #pragma unroll
        for (int o = 16; o; o >>= 1) lt += __shfl_xor_sync(~0u, lt, o);
        if (lane == 0) red[warp] = lt;
        __syncthreads();                         // publishes sw too
        if (tid == 0) {
            float L = red[0];
            #pragma unroll
            for (int i = 1; i < 8; i++) L += red[i];
            red[8] = L;
            out[OFF_M + n*S + q] = m + logf(L + 0.01f);
        }
        __syncthreads();
        float L = red[8];
        float acc = 0.f;
        #pragma unroll 8
        for (int k = 0; k < 48; k++) acc += wp[k] * Bp[k*H];
        if (g) zp[(g-1)*H + h] = acc;
        __syncthreads();
        if (!g)
            out[OFF_Z + (n*S + q)*H + h] =
                (acc + zp[0*H + h] + zp[1*H + h] + zp[2*H + h]) / L;
        __syncthreads();
    }
}

// ---------------------------------------------------------------------------
static int s_init = 0;

extern "C" void kernel_launch(void* const* d_in, const int* in_sizes, int n_in,
                              void* d_out, int out_size) {
    const float* q  = (const float*)d_in[0];
    const float* k1 = (const float*)d_in[1];
    const float* k2 = (const float*)d_in[2];
    const float* v1 = (const float*)d_in[3];
    const float* v2 = (const float*)d_in[4];
    float* out = (float*)d_out;

    if (!s_init) {   // host-side attribute set; done on the (uncaptured) correctness run
        cudaFuncSetAttribute(k_qz, cudaFuncAttributeMaxDynamicSharedMemorySize, 56*1024);
        s_init = 1;
    }
    const int QZ_SMEM = (SH + 3*S + 9 + 3*H) * sizeof(float);

    // prologue
    k_gram<<<dim3(12, 12, 16), dim3(16, 16)>>>(q, k1, k2);
    k_silu<<<(NH*SH)/256, 256>>>(v1);

    // big streaming writers first: their L2 write drain overlaps the small chain
    k_score <<<dim3(S, NH), 192>>>(out);
    k_vgated<<<dim3(S, NH), 256>>>(v2, out);

    // small compute chain (near-zero DRAM use, runs while writes drain)
    k_accumB<<<dim3(6, NH), 256>>>(v2);
    k_qz    <<<dim3(24, NH), 256, QZ_SMEM>>>(out);
}